// round 4
// baseline (speedup 1.0000x reference)
#include <cuda_runtime.h>
#include <cstdint>

#define N_BOX    2048
#define R_OUT    100
#define NTHREADS 256
#define EPT      8            // elements per thread
#define KMAX     160

typedef unsigned long long u64;
typedef unsigned int u32;

// Shared memory layout (dynamic, 44176 bytes):
//   sort: bufA u64[2048] @0, bufB u64[2048] @16384   (aliased by SoA below)
//   sl   f32[2048] @0       st f32[2048] @8192
//   sr   f32[2048] @16384   sb f32[2048] @24576
//   sha  f32[2048] @32768   (0.5f * area)
//   kL/kT/kR/kB2 f32[160] @40960/41600/42240/42880   (compact kept list)
//   smask  u32[32] @43520   sprior u32[32] @43648
//   kidx   int[100] @43776
#define SMEM_BYTES 44176

__device__ __forceinline__ void cmpex(u64& v, u64 u, bool lower, bool desc) {
    bool takeMax = (lower == desc);
    if (takeMax ? (u > v) : (u < v)) v = u;
}

__global__ __launch_bounds__(NTHREADS, 1)
void nms_kernel(const float* __restrict__ pred, float* __restrict__ out) {
    const int b    = blockIdx.x;
    const int tid  = threadIdx.x;
    const int lane = tid & 31;
    const int w    = tid >> 5;
    const float* p = pred + (size_t)b * N_BOX * 5;

    extern __shared__ unsigned char smem[];
    u64*  bufA = (u64*)smem;
    u64*  bufB = (u64*)(smem + 16384);
    float* sl   = (float*)(smem);
    float* st   = (float*)(smem + 8192);
    float* sr   = (float*)(smem + 16384);
    float* sb   = (float*)(smem + 24576);
    float* sha  = (float*)(smem + 32768);
    float* kL   = (float*)(smem + 40960);
    float* kT   = (float*)(smem + 41600);
    float* kR   = (float*)(smem + 42240);
    float* kB2  = (float*)(smem + 42880);
    u32*  smask  = (u32*)(smem + 43520);
    u32*  sprior = (u32*)(smem + 43648);
    int*  kidx   = (int*)(smem + 43776);
    __shared__ int s_kept;     // total greedy kept count
    __shared__ int s_nkept;    // compact kept list size
    __shared__ int s_stop;

    // ---- Phase 1: keys in registers, e = tid*8 + i.
    // (score desc, index asc tiebreak; scores in [0,1) -> raw bits order-preserving)
    u64 v[EPT];
    #pragma unroll
    for (int i = 0; i < EPT; ++i) {
        int e = tid * EPT + i;
        v[i] = (((u64)__float_as_uint(p[e * 5])) << 32) | (u64)(0xFFFFFFFFu - (u32)e);
    }

    // ---- Phase 2: bitonic sort, descending.
    //   j >= 256 : smem ping-pong (6 stages, 1 barrier each)
    //   8<=j<=128: intra-warp shfl (partner thread tid ^ (j>>3))
    //   j < 8    : intra-thread register exchange
    int bufsel = 0;
    for (int k = 2; k <= N_BOX; k <<= 1) {
        for (int j = k >> 1; j >= 256; j >>= 1) {
            u64* buf = bufsel ? bufB : bufA;
            #pragma unroll
            for (int i = 0; i < EPT; ++i) buf[tid * EPT + i] = v[i];
            __syncthreads();
            #pragma unroll
            for (int i = 0; i < EPT; ++i) {
                int e = tid * EPT + i;
                u64 u = buf[e ^ j];
                cmpex(v[i], u, (e & j) == 0, (e & k) == 0);
            }
            bufsel ^= 1;
        }
        for (int j = ((k >> 1) < 128 ? (k >> 1) : 128); j >= 8; j >>= 1) {
            int d = j >> 3;
            bool lower = (tid & d) == 0;
            #pragma unroll
            for (int i = 0; i < EPT; ++i) {
                u64 u = __shfl_xor_sync(0xFFFFFFFFu, v[i], d);
                int e = tid * EPT + i;
                cmpex(v[i], u, lower, (e & k) == 0);
            }
        }
        for (int j = ((k >> 1) < 4 ? (k >> 1) : 4); j >= 1; j >>= 1) {
            #pragma unroll
            for (int i = 0; i < EPT; ++i) {
                if ((i & j) == 0) {
                    int i2 = i | j;
                    int e = tid * EPT + i;
                    bool desc = ((e & k) == 0);
                    if (desc ? (v[i] < v[i2]) : (v[i] > v[i2])) {
                        u64 t = v[i]; v[i] = v[i2]; v[i2] = t;
                    }
                }
            }
        }
    }
    __syncthreads();   // last smem-stage reads done before SoA overwrite

    // ---- Phase 3: gather boxes into SoA by sorted rank
    #pragma unroll
    for (int i = 0; i < EPT; ++i) {
        int e = tid * EPT + i;
        u32 idx = 0xFFFFFFFFu - (u32)(v[i] & 0xFFFFFFFFu);
        const float* q = p + (size_t)idx * 5;
        float l = q[1], t = q[2], r = q[3], bo = q[4];
        sl[e] = l; st[e] = t; sr[e] = r; sb[e] = bo;
        sha[e] = 0.5f * ((r - l) * (bo - t));
    }
    if (tid == 0) { s_kept = 0; s_nkept = 0; s_stop = 0; }
    __syncthreads();

    // ---- Phase 4: on-demand chunked greedy (exact greedy equivalence).
    for (int base = 0; base < N_BOX; base += 32) {
        {   // Phase A: warp w owns columns c = 4w..4w+3 (chunk boxes);
            // lane = row (other chunk box) for the intra-chunk matrix.
            int nk = s_nkept;
            // column boxes (warp-uniform broadcast loads)
            float lc[4], tc[4], rc[4], bc4[4], hc[4];
            #pragma unroll
            for (int q = 0; q < 4; ++q) {
                int c = base + w * 4 + q;
                lc[q] = sl[c]; tc[q] = st[c]; rc[q] = sr[c]; bc4[q] = sb[c]; hc[q] = sha[c];
            }
            // suppressed-by-prior-kept test (lanes stride the compact list)
            bool sp[4] = {false, false, false, false};
            for (int kk = lane; kk < nk; kk += 32) {
                float kl = kL[kk], kt = kT[kk], kr = kR[kk], kb_ = kB2[kk];
                #pragma unroll
                for (int q = 0; q < 4; ++q) {
                    float iw = fminf(rc[q], kr) - fmaxf(lc[q], kl);
                    float ih = fminf(bc4[q], kb_) - fmaxf(tc[q], kt);
                    sp[q] |= (fmaxf(iw, 0.0f) * fmaxf(ih, 0.0f) >= hc[q]);
                }
            }
            // intra-chunk 32x32 matrix rows
            int ar = base + lane;
            float rl = sl[ar], rt = st[ar], rr = sr[ar], rb = sb[ar];
            #pragma unroll
            for (int q = 0; q < 4; ++q) {
                float iw = fminf(rc[q], rr) - fmaxf(lc[q], rl);
                float ih = fminf(bc4[q], rb) - fmaxf(tc[q], rt);
                u32 m   = __ballot_sync(0xFFFFFFFFu, fmaxf(iw, 0.0f) * fmaxf(ih, 0.0f) >= hc[q]);
                u32 spm = __ballot_sync(0xFFFFFFFFu, sp[q]);
                if (lane == 0) { smask[w * 4 + q] = m; sprior[w * 4 + q] = spm; }
            }
        }
        __syncthreads();
        if (w == 0) {   // Phase B: greedy resolve (all lanes redundant; broadcast reads)
            int nb  = s_nkept;
            int cnt = s_kept;
            u32 kb = 0;
            #pragma unroll
            for (int a = 0; a < 32; ++a) {
                if (sprior[a] == 0 && (smask[a] & kb) == 0) {
                    kb |= (1u << a);
                    if (cnt < R_OUT && lane == 0) kidx[cnt] = base + a;
                    cnt++;
                }
            }
            bool stop = (cnt >= R_OUT);
            __syncwarp();
            if (!stop && ((kb >> lane) & 1)) {
                int slot = nb + __popc(kb & ((1u << lane) - 1));
                int i = base + lane;
                kL[slot] = sl[i]; kT[slot] = st[i];
                kR[slot] = sr[i]; kB2[slot] = sb[i];
            }
            if (lane == 0) {
                s_kept  = cnt;
                s_nkept = nb + __popc(kb);
                s_stop  = stop;
            }
        }
        __syncthreads();
        if (s_stop) break;
    }

    // ---- Phase 5: output (top, right, bottom) for first R kept, zeros after
    int nk = s_kept; if (nk > R_OUT) nk = R_OUT;
    float* ob = out + (size_t)b * R_OUT * 3;
    if (tid < R_OUT) {
        int s = tid;
        if (s < nk) {
            int i = kidx[s];
            ob[s * 3 + 0] = st[i];
            ob[s * 3 + 1] = sr[i];
            ob[s * 3 + 2] = sb[i];
        } else {
            ob[s * 3 + 0] = 0.0f;
            ob[s * 3 + 1] = 0.0f;
            ob[s * 3 + 2] = 0.0f;
        }
    }
}

extern "C" void kernel_launch(void* const* d_in, const int* in_sizes, int n_in,
                              void* d_out, int out_size) {
    const float* pred = (const float*)d_in[0];
    float* out = (float*)d_out;
    (void)in_sizes; (void)n_in; (void)out_size;
    nms_kernel<<<32, NTHREADS, SMEM_BYTES>>>(pred, out);
}

// round 5
// speedup vs baseline: 2.9218x; 2.9218x over previous
#include <cuda_runtime.h>
#include <cstdint>

#define N_BOX   2048
#define R_OUT   100
#define NT      1024
#define TOPK    512
#define SEL_TGT 384

typedef unsigned long long u64;
typedef unsigned int u32;

// ---- shared memory layout (44176 bytes total) ----
// fast path:
//   keys  u64[2048] @0        (intact until fallback decision)
//   hist  u32[2048] @16384    (reused as skB u64[512] after scan)
//   sk    u64[512]  @24576
//   fsl/fst/fsr/fsb/fsha f32[512] @28672/30720/32768/34816/36864
//   fkL/fkT/fkR/fkB f32[160] @38912/39552/40192/40832
//   smaskF u32[32] @41472  spriorF u32[32] @41600
//   kidxF  int[100] @41728
//   wsum int[32] @42128  wpre int[32] @42256
// fallback (clobbers everything):
//   bufA u64[2048]@0  bufB u64[2048]@16384
//   sl2/st2/sr2/sb2/sha2 f32[2048] @0/8192/16384/24576/32768
//   kL2/kT2/kR2/kB2 f32[160] @40960/41600/42240/42880
//   smask2 @43520  sprior2 @43648  kidx2 @43776
#define SMEM_BYTES 44176

__device__ __forceinline__ void cmpex(u64& v, u64 u, bool lower, bool desc) {
    bool takeMax = (lower == desc);
    if (takeMax ? (u > v) : (u < v)) v = u;
}

__global__ __launch_bounds__(NT, 1)
void nms_kernel(const float* __restrict__ pred, float* __restrict__ out) {
    const int b    = blockIdx.x;
    const int tid  = threadIdx.x;
    const int lane = tid & 31;
    const int w    = tid >> 5;
    const u32 FULL = 0xFFFFFFFFu;
    const float* p = pred + (size_t)b * N_BOX * 5;

    extern __shared__ unsigned char smem[];
    u64*  keys = (u64*)(smem);
    u32*  hist = (u32*)(smem + 16384);
    u64*  skB  = (u64*)(smem + 16384);
    u64*  sk   = (u64*)(smem + 24576);
    float* fsl = (float*)(smem + 28672);
    float* fst = (float*)(smem + 30720);
    float* fsr = (float*)(smem + 32768);
    float* fsb = (float*)(smem + 34816);
    float* fsha= (float*)(smem + 36864);
    float* fkL = (float*)(smem + 38912);
    float* fkT = (float*)(smem + 39552);
    float* fkR = (float*)(smem + 40192);
    float* fkB = (float*)(smem + 40832);
    u32*  smaskF  = (u32*)(smem + 41472);
    u32*  spriorF = (u32*)(smem + 41600);
    int*  kidxF   = (int*)(smem + 41728);
    int*  wsum    = (int*)(smem + 42128);
    int*  wpre    = (int*)(smem + 42256);
    __shared__ int s_fb, s_T, s_M, s_cnt, s_kept, s_nkept, s_stop;

    if (tid == 0) { s_fb = 0; s_cnt = 0; s_kept = 0; s_nkept = 0; s_stop = 0; }
    hist[tid] = 0; hist[tid + NT] = 0;
    __syncthreads();

    // ---- Phase 1: build keys + histogram (score desc, idx asc tiebreak;
    // scores in [0,1) -> raw bits order-preserving)
    #pragma unroll
    for (int rep = 0; rep < 2; ++rep) {
        int e = tid + rep * NT;
        u32 sbits = __float_as_uint(p[e * 5]);
        keys[e] = ((u64)sbits << 32) | (u64)(0xFFFFFFFFu - (u32)e);
        atomicAdd(&hist[sbits >> 19], 1u);
    }
    __syncthreads();

    // ---- Phase 2: suffix scan over 2048 bins (pairs, top-down) -> threshold bin
    int hi = (int)hist[2047 - 2 * tid];
    int lo = (int)hist[2046 - 2 * tid];
    int sp = hi + lo;
    int x = sp;
    #pragma unroll
    for (int d = 1; d < 32; d <<= 1) { int y = __shfl_up_sync(FULL, x, d); if (lane >= d) x += y; }
    if (lane == 31) wsum[w] = x;
    __syncthreads();
    if (w == 0) {
        int t = wsum[lane];
        int xx = t;
        #pragma unroll
        for (int d = 1; d < 32; d <<= 1) { int y = __shfl_up_sync(FULL, xx, d); if (lane >= d) xx += y; }
        wpre[lane] = xx - t;
    }
    __syncthreads();
    {
        int incl = x + wpre[w];
        int excl = incl - sp;
        if (excl < SEL_TGT && incl >= SEL_TGT) {     // exactly one thread
            if (excl + hi >= SEL_TGT) { s_T = 2047 - 2 * tid; s_M = excl + hi; }
            else                      { s_T = 2046 - 2 * tid; s_M = incl; }
        }
    }
    __syncthreads();
    const int Tbin = s_T;
    const int M    = s_M;
    if (M > TOPK) { if (tid == 0) s_fb = 1; }
    __syncthreads();

    if (!s_fb) {
        // ---- Phase 3: warp-aggregated compaction of keys with bin >= Tbin
        #pragma unroll
        for (int rep = 0; rep < 2; ++rep) {
            int e = tid + rep * NT;
            u64 key = keys[e];
            bool q = (int)(u32)(key >> 51) >= Tbin;
            u32 bal = __ballot_sync(FULL, q);
            int rnk = __popc(bal & ((1u << lane) - 1));
            int basep = 0;
            if (lane == 0 && bal) basep = atomicAdd(&s_cnt, __popc(bal));
            basep = __shfl_sync(FULL, basep, 0);
            if (q) { int pos = basep + rnk; if (pos < TOPK) sk[pos] = key; }
        }
        __syncthreads();
        if (tid < TOPK && tid >= M) sk[tid] = 0;   // pad (sorts to tail)
        __syncthreads();

        // ---- Phase 4: bitonic sort of 512 keys, warps 0-7, named barrier(256)
        if (w < 8) {
            const int e0 = w * 64 + lane;
            const int e1 = e0 + 32;
            u64 v0 = sk[e0], v1 = sk[e1];
            int bufsel = 0;
            for (int k = 2; k <= TOPK; k <<= 1) {
                for (int j = k >> 1; j >= 64; j >>= 1) {
                    u64* buf = bufsel ? skB : sk;
                    buf[e0] = v0; buf[e1] = v1;
                    asm volatile("bar.sync 1, 256;" ::: "memory");
                    u64 u0 = buf[e0 ^ j];
                    u64 u1 = buf[e1 ^ j];
                    cmpex(v0, u0, (e0 & j) == 0, (e0 & k) == 0);
                    cmpex(v1, u1, (e1 & j) == 0, (e1 & k) == 0);
                    bufsel ^= 1;
                    asm volatile("bar.sync 1, 256;" ::: "memory");
                }
                if (k >= 64) {
                    bool desc = ((e0 & k) == 0);
                    if (desc ? (v0 < v1) : (v0 > v1)) { u64 t = v0; v0 = v1; v1 = t; }
                }
                for (int j = ((k >> 1) < 16 ? (k >> 1) : 16); j >= 1; j >>= 1) {
                    u64 u0 = __shfl_xor_sync(FULL, v0, j);
                    u64 u1 = __shfl_xor_sync(FULL, v1, j);
                    bool lower = (lane & j) == 0;
                    cmpex(v0, u0, lower, (e0 & k) == 0);
                    cmpex(v1, u1, lower, (e1 & k) == 0);
                }
            }
            sk[e0] = v0; sk[e1] = v1;
        }
        __syncthreads();

        // ---- Phase 5: gather top-512 boxes into SoA (all warps; pads -> zeros)
        if (tid < TOPK) {
            if (tid < M) {
                u32 idx = 0xFFFFFFFFu - (u32)(sk[tid] & 0xFFFFFFFFu);
                const float* q = p + (size_t)idx * 5;
                float l = q[1], t = q[2], r = q[3], bo = q[4];
                fsl[tid] = l; fst[tid] = t; fsr[tid] = r; fsb[tid] = bo;
                fsha[tid] = 0.5f * ((r - l) * (bo - t));
            } else {
                fsl[tid] = 0.0f; fst[tid] = 0.0f; fsr[tid] = 0.0f; fsb[tid] = 0.0f;
                fsha[tid] = 0.0f;
            }
        }
        __syncthreads();

        // ---- Phase 6: on-demand chunked greedy over sorted prefix (exact)
        for (int base = 0; base < TOPK; base += 32) {
            {   // A: warp w = column base+w; lane = row; + kept-list test
                int nk = s_nkept;
                int bc = base + w;
                float lb = fsl[bc], tb = fst[bc], rb = fsr[bc], bb = fsb[bc], hb = fsha[bc];
                bool spv = false;
                for (int kk = lane; kk < nk; kk += 32) {
                    float iw = fminf(rb, fkR[kk]) - fmaxf(lb, fkL[kk]);
                    float ih = fminf(bb, fkB[kk]) - fmaxf(tb, fkT[kk]);
                    spv |= (fmaxf(iw, 0.0f) * fmaxf(ih, 0.0f) >= hb);
                }
                int ar = base + lane;
                float iw = fminf(rb, fsr[ar]) - fmaxf(lb, fsl[ar]);
                float ih = fminf(bb, fsb[ar]) - fmaxf(tb, fst[ar]);
                u32 m   = __ballot_sync(FULL, fmaxf(iw, 0.0f) * fmaxf(ih, 0.0f) >= hb);
                u32 spm = __ballot_sync(FULL, spv);
                if (lane == 0) { smaskF[w] = m; spriorF[w] = spm; }
            }
            __syncthreads();
            if (w == 0) {   // B: greedy resolve, rank guard < M
                int nb  = s_nkept;
                int cnt = s_kept;
                u32 kb = 0;
                #pragma unroll
                for (int a = 0; a < 32; ++a) {
                    if (base + a < M && spriorF[a] == 0 && (smaskF[a] & kb) == 0) {
                        kb |= (1u << a);
                        if (cnt < R_OUT && lane == 0) kidxF[cnt] = base + a;
                        cnt++;
                    }
                }
                bool stop = (cnt >= R_OUT);
                __syncwarp();
                if (!stop && ((kb >> lane) & 1)) {
                    int slot = nb + __popc(kb & ((1u << lane) - 1));
                    int i = base + lane;
                    fkL[slot] = fsl[i]; fkT[slot] = fst[i];
                    fkR[slot] = fsr[i]; fkB[slot] = fsb[i];
                }
                if (lane == 0) {
                    s_kept  = cnt;
                    s_nkept = nb + __popc(kb);
                    s_stop  = stop;
                }
            }
            __syncthreads();
            if (s_stop) break;
        }
        if (tid == 0 && s_kept < R_OUT) s_fb = 1;   // prefix exhausted -> exact fallback
        __syncthreads();
    }

    // =================== FALLBACK: full exact path (R3) ===================
    if (s_fb) {
        u64*  bufA = (u64*)(smem);
        u64*  bufB = (u64*)(smem + 16384);
        float* sl2  = (float*)(smem);
        float* st2  = (float*)(smem + 8192);
        float* sr2  = (float*)(smem + 16384);
        float* sb2  = (float*)(smem + 24576);
        float* sha2 = (float*)(smem + 32768);
        float* kL2  = (float*)(smem + 40960);
        float* kT2  = (float*)(smem + 41600);
        float* kR2  = (float*)(smem + 42240);
        float* kB2  = (float*)(smem + 42880);
        u32*  smask2  = (u32*)(smem + 43520);
        u32*  sprior2 = (u32*)(smem + 43648);
        int*  kidx2   = (int*)(smem + 43776);

        const int e0 = w * 64 + lane;
        const int e1 = e0 + 32;
        u64 v0 = keys[e0];
        u64 v1 = keys[e1];
        __syncthreads();

        int bufsel = 0;
        for (int k = 2; k <= N_BOX; k <<= 1) {
            for (int j = k >> 1; j >= 64; j >>= 1) {
                u64* buf = bufsel ? bufB : bufA;
                buf[e0] = v0; buf[e1] = v1;
                __syncthreads();
                u64 u0 = buf[e0 ^ j];
                u64 u1 = buf[e1 ^ j];
                cmpex(v0, u0, (e0 & j) == 0, (e0 & k) == 0);
                cmpex(v1, u1, (e1 & j) == 0, (e1 & k) == 0);
                bufsel ^= 1;
                __syncthreads();
            }
            if (k >= 64) {
                bool desc = ((e0 & k) == 0);
                if (desc ? (v0 < v1) : (v0 > v1)) { u64 t = v0; v0 = v1; v1 = t; }
            }
            for (int j = ((k >> 1) < 16 ? (k >> 1) : 16); j >= 1; j >>= 1) {
                u64 u0 = __shfl_xor_sync(FULL, v0, j);
                u64 u1 = __shfl_xor_sync(FULL, v1, j);
                bool lower = (lane & j) == 0;
                cmpex(v0, u0, lower, (e0 & k) == 0);
                cmpex(v1, u1, lower, (e1 & k) == 0);
            }
        }
        __syncthreads();

        {
            u32 i0 = 0xFFFFFFFFu - (u32)(v0 & 0xFFFFFFFFu);
            u32 i1 = 0xFFFFFFFFu - (u32)(v1 & 0xFFFFFFFFu);
            const float* q = p + (size_t)i0 * 5;
            float l = q[1], t = q[2], r = q[3], bo = q[4];
            sl2[e0] = l; st2[e0] = t; sr2[e0] = r; sb2[e0] = bo;
            sha2[e0] = 0.5f * ((r - l) * (bo - t));
            q = p + (size_t)i1 * 5;
            l = q[1]; t = q[2]; r = q[3]; bo = q[4];
            sl2[e1] = l; st2[e1] = t; sr2[e1] = r; sb2[e1] = bo;
            sha2[e1] = 0.5f * ((r - l) * (bo - t));
        }
        if (tid == 0) { s_kept = 0; s_nkept = 0; s_stop = 0; }
        __syncthreads();

        for (int base = 0; base < N_BOX; base += 32) {
            {
                int nk = s_nkept;
                int bc = base + w;
                float lb = sl2[bc], tb = st2[bc], rb = sr2[bc], bb = sb2[bc], hb = sha2[bc];
                bool spv = false;
                for (int kk = lane; kk < nk; kk += 32) {
                    float iw = fminf(rb, kR2[kk]) - fmaxf(lb, kL2[kk]);
                    float ih = fminf(bb, kB2[kk]) - fmaxf(tb, kT2[kk]);
                    spv |= (fmaxf(iw, 0.0f) * fmaxf(ih, 0.0f) >= hb);
                }
                int ar = base + lane;
                float iw = fminf(rb, sr2[ar]) - fmaxf(lb, sl2[ar]);
                float ih = fminf(bb, sb2[ar]) - fmaxf(tb, st2[ar]);
                u32 m   = __ballot_sync(FULL, fmaxf(iw, 0.0f) * fmaxf(ih, 0.0f) >= hb);
                u32 spm = __ballot_sync(FULL, spv);
                if (lane == 0) { smask2[w] = m; sprior2[w] = spm; }
            }
            __syncthreads();
            if (w == 0) {
                int nb  = s_nkept;
                int cnt = s_kept;
                u32 kb = 0;
                #pragma unroll
                for (int a = 0; a < 32; ++a) {
                    if (sprior2[a] == 0 && (smask2[a] & kb) == 0) {
                        kb |= (1u << a);
                        if (cnt < R_OUT && lane == 0) kidx2[cnt] = base + a;
                        cnt++;
                    }
                }
                bool stop = (cnt >= R_OUT);
                __syncwarp();
                if (!stop && ((kb >> lane) & 1)) {
                    int slot = nb + __popc(kb & ((1u << lane) - 1));
                    int i = base + lane;
                    kL2[slot] = sl2[i]; kT2[slot] = st2[i];
                    kR2[slot] = sr2[i]; kB2[slot] = sb2[i];
                }
                if (lane == 0) {
                    s_kept  = cnt;
                    s_nkept = nb + __popc(kb);
                    s_stop  = stop;
                }
            }
            __syncthreads();
            if (s_stop) break;
        }
        __syncthreads();

        // fallback output
        int nk = s_kept; if (nk > R_OUT) nk = R_OUT;
        float* ob = out + (size_t)b * R_OUT * 3;
        if (tid < R_OUT) {
            int s = tid;
            if (s < nk) {
                int i = kidx2[s];
                ob[s * 3 + 0] = st2[i];
                ob[s * 3 + 1] = sr2[i];
                ob[s * 3 + 2] = sb2[i];
            } else {
                ob[s * 3 + 0] = 0.0f;
                ob[s * 3 + 1] = 0.0f;
                ob[s * 3 + 2] = 0.0f;
            }
        }
        return;
    }

    // ---- fast-path output: (top, right, bottom) for first R kept, zeros after
    int nk = s_kept; if (nk > R_OUT) nk = R_OUT;
    float* ob = out + (size_t)b * R_OUT * 3;
    if (tid < R_OUT) {
        int s = tid;
        if (s < nk) {
            int i = kidxF[s];
            ob[s * 3 + 0] = fst[i];
            ob[s * 3 + 1] = fsr[i];
            ob[s * 3 + 2] = fsb[i];
        } else {
            ob[s * 3 + 0] = 0.0f;
            ob[s * 3 + 1] = 0.0f;
            ob[s * 3 + 2] = 0.0f;
        }
    }
}

extern "C" void kernel_launch(void* const* d_in, const int* in_sizes, int n_in,
                              void* d_out, int out_size) {
    const float* pred = (const float*)d_in[0];
    float* out = (float*)d_out;
    (void)in_sizes; (void)n_in; (void)out_size;
    nms_kernel<<<32, NT, SMEM_BYTES>>>(pred, out);
}

// round 8
// speedup vs baseline: 3.1787x; 1.0879x over previous
#include <cuda_runtime.h>
#include <cstdint>

#define N_BOX   2048
#define R_OUT   100
#define NT      1024
#define TOPK    256
#define SEL_TGT 192

typedef unsigned long long u64;
typedef unsigned int u32;

// ---- shared memory layout ----
// fast path:
//   keys  u64[2048] @0        (intact until fallback decision)
//   hist  u32[4096] @16384    (16KB)
//   sk    u64[256]  @32768    skB u64[256] @34816
//   fsl/fst/fsr/fsb/fsha f32[256] @36864/37888/38912/39936/40960
//   fkL/fkT/fkR/fkB f32[160] @41984/42624/43264/43904
//   smaskF u32[32] @44544  spriorF u32[32] @44672
//   kidxF  int[100] @44800
//   wsum int[32] @45200  wpre int[32] @45328
// fallback (clobbers everything): same as R3 layout
#define SMEM_BYTES 45456

__device__ __forceinline__ void cmpex(u64& v, u64 u, bool lower, bool desc) {
    bool takeMax = (lower == desc);
    if (takeMax ? (u > v) : (u < v)) v = u;
}

__global__ __launch_bounds__(NT, 1)
void nms_kernel(const float* __restrict__ pred, float* __restrict__ out) {
    const int b    = blockIdx.x;
    const int tid  = threadIdx.x;
    const int lane = tid & 31;
    const int w    = tid >> 5;
    const u32 FULL = 0xFFFFFFFFu;
    const float* p = pred + (size_t)b * N_BOX * 5;

    extern __shared__ unsigned char smem[];
    u64*  keys = (u64*)(smem);
    u32*  hist = (u32*)(smem + 16384);
    u64*  sk   = (u64*)(smem + 32768);
    u64*  skB  = (u64*)(smem + 34816);
    float* fsl = (float*)(smem + 36864);
    float* fst = (float*)(smem + 37888);
    float* fsr = (float*)(smem + 38912);
    float* fsb = (float*)(smem + 39936);
    float* fsha= (float*)(smem + 40960);
    float* fkL = (float*)(smem + 41984);
    float* fkT = (float*)(smem + 42624);
    float* fkR = (float*)(smem + 43264);
    float* fkB = (float*)(smem + 43904);
    u32*  smaskF  = (u32*)(smem + 44544);
    u32*  spriorF = (u32*)(smem + 44672);
    int*  kidxF   = (int*)(smem + 44800);
    int*  wsum    = (int*)(smem + 45200);
    int*  wpre    = (int*)(smem + 45328);
    __shared__ int s_fb, s_T, s_M, s_cnt, s_kept, s_nkept, s_stop;

    if (tid == 0) { s_fb = 0; s_cnt = 0; s_kept = 0; s_nkept = 0; s_stop = 0; }
    ((uint4*)hist)[tid] = make_uint4(0, 0, 0, 0);   // 4096 bins zeroed
    __syncthreads();

    // ---- Phase 1: keys + 4096-bin histogram (score bits >>18; order-preserving)
    #pragma unroll
    for (int rep = 0; rep < 2; ++rep) {
        int e = tid + rep * NT;
        u32 sbits = __float_as_uint(p[e * 5]);
        keys[e] = ((u64)sbits << 32) | (u64)(0xFFFFFFFFu - (u32)e);
        atomicAdd(&hist[sbits >> 18], 1u);
    }
    __syncthreads();

    // ---- Phase 2: suffix scan over 4096 bins (4 per thread, top-down)
    int b0 = 4095 - 4 * tid;
    int c0 = (int)hist[b0], c1 = (int)hist[b0 - 1], c2 = (int)hist[b0 - 2], c3 = (int)hist[b0 - 3];
    int sp = c0 + c1 + c2 + c3;
    int x = sp;
    #pragma unroll
    for (int d = 1; d < 32; d <<= 1) { int y = __shfl_up_sync(FULL, x, d); if (lane >= d) x += y; }
    if (lane == 31) wsum[w] = x;
    __syncthreads();
    if (w == 0) {
        int t = wsum[lane];
        int xx = t;
        #pragma unroll
        for (int d = 1; d < 32; d <<= 1) { int y = __shfl_up_sync(FULL, xx, d); if (lane >= d) xx += y; }
        wpre[lane] = xx - t;
    }
    __syncthreads();
    {
        int incl = x + wpre[w];
        int excl = incl - sp;
        if (excl < SEL_TGT && incl >= SEL_TGT) {     // exactly one thread
            int a0 = excl + c0, a1 = a0 + c1, a2 = a1 + c2;
            if      (a0 >= SEL_TGT) { s_T = b0;     s_M = a0; }
            else if (a1 >= SEL_TGT) { s_T = b0 - 1; s_M = a1; }
            else if (a2 >= SEL_TGT) { s_T = b0 - 2; s_M = a2; }
            else                    { s_T = b0 - 3; s_M = incl; }
        }
    }
    __syncthreads();
    const int Tbin = s_T;
    const int M    = s_M;
    if (M > TOPK) { if (tid == 0) s_fb = 1; }
    __syncthreads();

    if (!s_fb) {
        // ---- Phase 3: warp-aggregated compaction (bin >= Tbin) + pad in same phase
        if (tid >= M && tid < TOPK) sk[tid] = 0;     // pads sort to tail
        #pragma unroll
        for (int rep = 0; rep < 2; ++rep) {
            int e = tid + rep * NT;
            u64 key = keys[e];
            bool q = (int)(u32)(key >> 50) >= Tbin;
            u32 bal = __ballot_sync(FULL, q);
            int rnk = __popc(bal & ((1u << lane) - 1));
            int basep = 0;
            if (lane == 0 && bal) basep = atomicAdd(&s_cnt, __popc(bal));
            basep = __shfl_sync(FULL, basep, 0);
            if (q) { int pos = basep + rnk; if (pos < TOPK) sk[pos] = key; }
        }
        __syncthreads();

        // ---- Phase 4: bitonic sort of 256 keys, warps 0-3 (128 thr, 2 elt/thr)
        // smem stages (j>=64): k=128 -> 1, k=256 -> 2. One named barrier each
        // (write->bar->read is safe: a buffer's re-write is separated from all
        //  its reads by the next stage's barrier via ping-pong).
        if (w < 4) {
            const int e0 = w * 64 + lane;
            const int e1 = e0 + 32;
            u64 v0 = sk[e0], v1 = sk[e1];
            int bufsel = 0;
            for (int k = 2; k <= TOPK; k <<= 1) {
                for (int j = k >> 1; j >= 64; j >>= 1) {
                    u64* buf = bufsel ? skB : sk;
                    buf[e0] = v0; buf[e1] = v1;
                    asm volatile("bar.sync 1, 128;" ::: "memory");
                    u64 u0 = buf[e0 ^ j];
                    u64 u1 = buf[e1 ^ j];
                    cmpex(v0, u0, (e0 & j) == 0, (e0 & k) == 0);
                    cmpex(v1, u1, (e1 & j) == 0, (e1 & k) == 0);
                    bufsel ^= 1;
                }
                if (k >= 64) {
                    bool desc = ((e0 & k) == 0);
                    if (desc ? (v0 < v1) : (v0 > v1)) { u64 t = v0; v0 = v1; v1 = t; }
                }
                for (int j = ((k >> 1) < 16 ? (k >> 1) : 16); j >= 1; j >>= 1) {
                    u64 u0 = __shfl_xor_sync(FULL, v0, j);
                    u64 u1 = __shfl_xor_sync(FULL, v1, j);
                    bool lower = (lane & j) == 0;
                    cmpex(v0, u0, lower, (e0 & k) == 0);
                    cmpex(v1, u1, lower, (e1 & k) == 0);
                }
            }
            asm volatile("bar.sync 1, 128;" ::: "memory");  // last stage reads done
            sk[e0] = v0; sk[e1] = v1;
        }
        __syncthreads();

        // ---- Phase 5: gather top-256 boxes into SoA (pads -> zeros)
        if (tid < TOPK) {
            if (tid < M) {
                u32 idx = 0xFFFFFFFFu - (u32)(sk[tid] & 0xFFFFFFFFu);
                const float* q = p + (size_t)idx * 5;
                float l = q[1], t = q[2], r = q[3], bo = q[4];
                fsl[tid] = l; fst[tid] = t; fsr[tid] = r; fsb[tid] = bo;
                fsha[tid] = 0.5f * ((r - l) * (bo - t));
            } else {
                fsl[tid] = 0.0f; fst[tid] = 0.0f; fsr[tid] = 0.0f; fsb[tid] = 0.0f;
                fsha[tid] = 0.0f;
            }
        }
        __syncthreads();

        // ---- Phase 6: on-demand chunked greedy over sorted prefix (exact)
        for (int base = 0; base < TOPK; base += 32) {
            {   // A: warp w = column base+w; lane = row; + kept-list test
                int nk = s_nkept;
                int bc = base + w;
                float lb = fsl[bc], tb = fst[bc], rb = fsr[bc], bb = fsb[bc], hb = fsha[bc];
                bool spv = false;
                for (int kk = lane; kk < nk; kk += 32) {
                    float iw = fminf(rb, fkR[kk]) - fmaxf(lb, fkL[kk]);
                    float ih = fminf(bb, fkB[kk]) - fmaxf(tb, fkT[kk]);
                    spv |= (fmaxf(iw, 0.0f) * fmaxf(ih, 0.0f) >= hb);
                }
                int ar = base + lane;
                float iw = fminf(rb, fsr[ar]) - fmaxf(lb, fsl[ar]);
                float ih = fminf(bb, fsb[ar]) - fmaxf(tb, fst[ar]);
                u32 m   = __ballot_sync(FULL, fmaxf(iw, 0.0f) * fmaxf(ih, 0.0f) >= hb);
                u32 spm = __ballot_sync(FULL, spv);
                if (lane == 0) { smaskF[w] = m; spriorF[w] = spm; }
            }
            __syncthreads();
            if (w == 0) {   // B: greedy resolve, rank guard < M
                int nb  = s_nkept;
                int cnt = s_kept;
                u32 kb = 0;
                #pragma unroll
                for (int a = 0; a < 32; ++a) {
                    if (base + a < M && spriorF[a] == 0 && (smaskF[a] & kb) == 0) {
                        kb |= (1u << a);
                        if (cnt < R_OUT && lane == 0) kidxF[cnt] = base + a;
                        cnt++;
                    }
                }
                bool stop = (cnt >= R_OUT);
                __syncwarp();
                if (!stop && ((kb >> lane) & 1)) {
                    int slot = nb + __popc(kb & ((1u << lane) - 1));
                    int i = base + lane;
                    fkL[slot] = fsl[i]; fkT[slot] = fst[i];
                    fkR[slot] = fsr[i]; fkB[slot] = fsb[i];
                }
                if (lane == 0) {
                    s_kept  = cnt;
                    s_nkept = nb + __popc(kb);
                    s_stop  = stop;
                }
            }
            __syncthreads();
            if (s_stop) break;
        }
        if (tid == 0 && s_kept < R_OUT) s_fb = 1;   // prefix exhausted -> exact fallback
        __syncthreads();
    }

    // =================== FALLBACK: full exact path ===================
    if (s_fb) {
        u64*  bufA = (u64*)(smem);
        u64*  bufB = (u64*)(smem + 16384);
        float* sl2  = (float*)(smem);
        float* st2  = (float*)(smem + 8192);
        float* sr2  = (float*)(smem + 16384);
        float* sb2  = (float*)(smem + 24576);
        float* sha2 = (float*)(smem + 32768);
        float* kL2  = (float*)(smem + 40960);
        float* kT2  = (float*)(smem + 41600);
        float* kR2  = (float*)(smem + 42240);
        float* kB2  = (float*)(smem + 42880);
        u32*  smask2  = (u32*)(smem + 43520);
        u32*  sprior2 = (u32*)(smem + 43648);
        int*  kidx2   = (int*)(smem + 43776);

        const int e0 = w * 64 + lane;
        const int e1 = e0 + 32;
        u64 v0 = keys[e0];
        u64 v1 = keys[e1];
        __syncthreads();

        int bufsel = 0;
        for (int k = 2; k <= N_BOX; k <<= 1) {
            for (int j = k >> 1; j >= 64; j >>= 1) {
                u64* buf = bufsel ? bufB : bufA;
                buf[e0] = v0; buf[e1] = v1;
                __syncthreads();
                u64 u0 = buf[e0 ^ j];
                u64 u1 = buf[e1 ^ j];
                cmpex(v0, u0, (e0 & j) == 0, (e0 & k) == 0);
                cmpex(v1, u1, (e1 & j) == 0, (e1 & k) == 0);
                bufsel ^= 1;
                __syncthreads();
            }
            if (k >= 64) {
                bool desc = ((e0 & k) == 0);
                if (desc ? (v0 < v1) : (v0 > v1)) { u64 t = v0; v0 = v1; v1 = t; }
            }
            for (int j = ((k >> 1) < 16 ? (k >> 1) : 16); j >= 1; j >>= 1) {
                u64 u0 = __shfl_xor_sync(FULL, v0, j);
                u64 u1 = __shfl_xor_sync(FULL, v1, j);
                bool lower = (lane & j) == 0;
                cmpex(v0, u0, lower, (e0 & k) == 0);
                cmpex(v1, u1, lower, (e1 & k) == 0);
            }
        }
        __syncthreads();

        {
            u32 i0 = 0xFFFFFFFFu - (u32)(v0 & 0xFFFFFFFFu);
            u32 i1 = 0xFFFFFFFFu - (u32)(v1 & 0xFFFFFFFFu);
            const float* q = p + (size_t)i0 * 5;
            float l = q[1], t = q[2], r = q[3], bo = q[4];
            sl2[e0] = l; st2[e0] = t; sr2[e0] = r; sb2[e0] = bo;
            sha2[e0] = 0.5f * ((r - l) * (bo - t));
            q = p + (size_t)i1 * 5;
            l = q[1]; t = q[2]; r = q[3]; bo = q[4];
            sl2[e1] = l; st2[e1] = t; sr2[e1] = r; sb2[e1] = bo;
            sha2[e1] = 0.5f * ((r - l) * (bo - t));
        }
        if (tid == 0) { s_kept = 0; s_nkept = 0; s_stop = 0; }
        __syncthreads();

        for (int base = 0; base < N_BOX; base += 32) {
            {
                int nk = s_nkept;
                int bc = base + w;
                float lb = sl2[bc], tb = st2[bc], rb = sr2[bc], bb = sb2[bc], hb = sha2[bc];
                bool spv = false;
                for (int kk = lane; kk < nk; kk += 32) {
                    float iw = fminf(rb, kR2[kk]) - fmaxf(lb, kL2[kk]);
                    float ih = fminf(bb, kB2[kk]) - fmaxf(tb, kT2[kk]);
                    spv |= (fmaxf(iw, 0.0f) * fmaxf(ih, 0.0f) >= hb);
                }
                int ar = base + lane;
                float iw = fminf(rb, sr2[ar]) - fmaxf(lb, sl2[ar]);
                float ih = fminf(bb, sb2[ar]) - fmaxf(tb, st2[ar]);
                u32 m   = __ballot_sync(FULL, fmaxf(iw, 0.0f) * fmaxf(ih, 0.0f) >= hb);
                u32 spm = __ballot_sync(FULL, spv);
                if (lane == 0) { smask2[w] = m; sprior2[w] = spm; }
            }
            __syncthreads();
            if (w == 0) {
                int nb  = s_nkept;
                int cnt = s_kept;
                u32 kb = 0;
                #pragma unroll
                for (int a = 0; a < 32; ++a) {
                    if (sprior2[a] == 0 && (smask2[a] & kb) == 0) {
                        kb |= (1u << a);
                        if (cnt < R_OUT && lane == 0) kidx2[cnt] = base + a;
                        cnt++;
                    }
                }
                bool stop = (cnt >= R_OUT);
                __syncwarp();
                if (!stop && ((kb >> lane) & 1)) {
                    int slot = nb + __popc(kb & ((1u << lane) - 1));
                    int i = base + lane;
                    kL2[slot] = sl2[i]; kT2[slot] = st2[i];
                    kR2[slot] = sr2[i]; kB2[slot] = sb2[i];
                }
                if (lane == 0) {
                    s_kept  = cnt;
                    s_nkept = nb + __popc(kb);
                    s_stop  = stop;
                }
            }
            __syncthreads();
            if (s_stop) break;
        }
        __syncthreads();

        int nk = s_kept; if (nk > R_OUT) nk = R_OUT;
        float* ob = out + (size_t)b * R_OUT * 3;
        if (tid < R_OUT) {
            int s = tid;
            if (s < nk) {
                int i = kidx2[s];
                ob[s * 3 + 0] = st2[i];
                ob[s * 3 + 1] = sr2[i];
                ob[s * 3 + 2] = sb2[i];
            } else {
                ob[s * 3 + 0] = 0.0f;
                ob[s * 3 + 1] = 0.0f;
                ob[s * 3 + 2] = 0.0f;
            }
        }
        return;
    }

    // ---- fast-path output: (top, right, bottom) for first R kept, zeros after
    int nk = s_kept; if (nk > R_OUT) nk = R_OUT;
    float* ob = out + (size_t)b * R_OUT * 3;
    if (tid < R_OUT) {
        int s = tid;
        if (s < nk) {
            int i = kidxF[s];
            ob[s * 3 + 0] = fst[i];
            ob[s * 3 + 1] = fsr[i];
            ob[s * 3 + 2] = fsb[i];
        } else {
            ob[s * 3 + 0] = 0.0f;
            ob[s * 3 + 1] = 0.0f;
            ob[s * 3 + 2] = 0.0f;
        }
    }
}

extern "C" void kernel_launch(void* const* d_in, const int* in_sizes, int n_in,
                              void* d_out, int out_size) {
    const float* pred = (const float*)d_in[0];
    float* out = (float*)d_out;
    (void)in_sizes; (void)n_in; (void)out_size;
    nms_kernel<<<32, NT, SMEM_BYTES>>>(pred, out);
}